// round 16
// baseline (speedup 1.0000x reference)
#include <cuda_runtime.h>
#include <cstdint>

#define BATCH 2
#define SEQ   2048
#define DIM   2048
#define NH    16
#define NKV   4
#define HD    128
#define QDIM  (NH*HD)      // 2048
#define KVDIM (2*NKV*HD)   // 1024
#define ROWS  (BATCH*SEQ)  // 4096

// Scratch (allocation-free rule: __device__ globals)
// K-PERMUTED layouts (per 8-elem k-group: [k0,k4,k1,k5,k2,k6,k3,k7]):
//   x32, wqt, wkvt, wot, vo            (gemm K dim)
//   g_q and K-half of g_kv (head dim)  (flash QK k dim)
__device__ float g_x32[(size_t)ROWS*DIM];
__device__ float g_q  [(size_t)ROWS*QDIM];
__device__ float g_kv [(size_t)ROWS*KVDIM];
__device__ float g_vo [(size_t)ROWS*QDIM];
__device__ float g_wqt [(size_t)DIM*QDIM];
__device__ float g_wkvt[(size_t)DIM*KVDIM];
__device__ float g_wot [(size_t)QDIM*DIM];

__device__ __forceinline__ uint32_t tf32_rna(float x) {
    uint32_t y;
    asm("cvt.rna.tf32.f32 %0, %1;" : "=r"(y) : "f"(x));
    return y;
}
__device__ __forceinline__ float tf32f(float x) {
    return __uint_as_float(tf32_rna(x));
}
__device__ __forceinline__ float ex2f(float x) {
    float y;
    asm("ex2.approx.ftz.f32 %0, %1;" : "=f"(y) : "f"(x));
    return y;
}
// slot(j) = ((j&3)<<1) | (j>>2)  for j in 0..7  -> [0,2,4,6,1,3,5,7]
__device__ __forceinline__ int kslot(int j) { return ((j & 3) << 1) | (j >> 2); }

#define MMA_TF32(c, a, b0, b1)                                                \
    asm volatile("mma.sync.aligned.m16n8k8.row.col.f32.tf32.tf32.f32 "        \
        "{%0,%1,%2,%3},{%4,%5,%6,%7},{%8,%9},{%0,%1,%2,%3};"                  \
        : "+f"((c)[0]), "+f"((c)[1]), "+f"((c)[2]), "+f"((c)[3])              \
        : "r"((a)[0]), "r"((a)[1]), "r"((a)[2]), "r"((a)[3]),                 \
          "r"(b0), "r"(b1))

#define CP16(d, s)   asm volatile("cp.async.cg.shared.global [%0], [%1], 16;" :: "r"(d), "l"(s))
#define CP_COMMIT()  asm volatile("cp.async.commit_group;")
#define CP_WAIT0()   asm volatile("cp.async.wait_group 0;")
#define CP_WAIT1()   asm volatile("cp.async.wait_group 1;")
#define CP_WAIT2()   asm volatile("cp.async.wait_group 2;")
#define SPTR(p)      ((uint32_t)__cvta_generic_to_shared(p))

// ---------------------------------------------------------------------------
// rna-convert x -> K-permuted layout
// ---------------------------------------------------------------------------
__global__ void cvt_tf32_kernel(const float* __restrict__ src,
                                float* __restrict__ dst, int n4)
{
    int i = blockIdx.x * blockDim.x + threadIdx.x;
    if (i < n4) {
        float4 v = ((const float4*)src)[i];
        size_t base = ((size_t)(i >> 1) << 3) + (i & 1);
        dst[base + 0] = tf32f(v.x);
        dst[base + 2] = tf32f(v.y);
        dst[base + 4] = tf32f(v.z);
        dst[base + 6] = tf32f(v.w);
    }
}

// ---------------------------------------------------------------------------
// Merged weight transpose + rna + K-permute: W[K,N] -> Wt[N,K]  (3 matrices)
// ---------------------------------------------------------------------------
__global__ void transpose_w_kernel(
    const float* __restrict__ Wq, const float* __restrict__ Wkv,
    const float* __restrict__ Wo,
    float* __restrict__ wqt, float* __restrict__ wkvt, float* __restrict__ wot)
{
    const float* src; float* dst; int K, N;
    if (blockIdx.z == 0)      { src = Wq;  dst = wqt;  K = DIM;  N = QDIM; }
    else if (blockIdx.z == 1) { src = Wkv; dst = wkvt; K = DIM;  N = KVDIM; }
    else                      { src = Wo;  dst = wot;  K = QDIM; N = DIM; }
    int n0 = blockIdx.x * 32, k0 = blockIdx.y * 32;
    if (n0 >= N || k0 >= K) return;

    __shared__ float t[32][33];
    int x = threadIdx.x, y = threadIdx.y;     // 32 x 8
#pragma unroll
    for (int i = 0; i < 32; i += 8)
        t[y + i][x] = src[(size_t)(k0 + y + i) * N + n0 + x];
    __syncthreads();
    int px = (x & 24) + kslot(x & 7);
#pragma unroll
    for (int i = 0; i < 32; i += 8)
        dst[(size_t)(n0 + y + i) * K + k0 + px] = tf32f(t[x][y + i]);
}

// ---------------------------------------------------------------------------
// Shared GEMM body (tf32 mma.sync, K-PERMUTED inputs, BK=16, FOUR-stage
// cp.async pipeline, 128x128 tile, 8 warps of 64x32).
// Epilogue MODE: 0 = plain+bias (out-proj)
//               1 = rna(acc+bias)            (V part of KV proj)
//               2 = RoPE+rna via smem stage  (Q / K; ropescale differs)
// ---------------------------------------------------------------------------
#define STG_WORDS 4096
#define GEMM_SMEM (16640*4)              // max(4*4096, 128*130) words = 66560 B

template<int MODE>
__device__ __forceinline__ void gemm_body(
    uint32_t* gsm,
    const float* __restrict__ Ag,
    const float* __restrict__ Bg,
    const float* __restrict__ bias,
    float* __restrict__ C,
    size_t brow0, int bcol0, int N, int K,
    const float* __restrict__ cs, const float* __restrict__ sn,
    float ropescale)
{
    const int tid  = threadIdx.x;
    const int lane = tid & 31, wid = tid >> 5;
    const int warp_m = (wid >> 2) << 6;
    const int warp_n = (wid & 3) << 5;
    const int g8 = lane >> 2, tg = lane & 3;
    const int sw   = g8 & 3;
    const int coff = (tg << 1) & 3;
    const int cb0  = tg >> 1;

    const int r0 = tid >> 2, cch = tid & 3;
    const int dxor = ((cch ^ (r0 & 3)) << 2);
    const int nk = K >> 4;

    auto issue = [&](int kt, int s) {
        uint32_t* Ad = gsm + s * STG_WORDS;
        uint32_t* Bd = Ad + 2048;
        const float* ap = Ag + (size_t)r0 * K + (kt << 4) + (cch << 2);
        const float* bp = Bg + (size_t)r0 * K + (kt << 4) + (cch << 2);
        CP16(SPTR(&Ad[(r0 << 4) + dxor]),        ap);
        CP16(SPTR(&Ad[((r0 + 64) << 4) + dxor]), ap + (size_t)64 * K);
        CP16(SPTR(&Bd[(r0 << 4) + dxor]),        bp);
        CP16(SPTR(&Bd[((r0 + 64) << 4) + dxor]), bp + (size_t)64 * K);
    };

    float acc[4][4][4];
#pragma unroll
    for (int i = 0; i < 4; i++)
#pragma unroll
        for (int j = 0; j < 4; j++)
#pragma unroll
            for (int c = 0; c < 4; c++) acc[i][j][c] = 0.f;

    issue(0, 0); CP_COMMIT();
    issue(1, 1); CP_COMMIT();
    issue(2, 2); CP_COMMIT();

    for (int kt = 0; kt < nk; kt++) {
        CP_WAIT2();
        __syncthreads();
        if (kt + 3 < nk) issue(kt + 3, (kt + 3) & 3);
        CP_COMMIT();

        const uint32_t* Ab = gsm + (kt & 3) * STG_WORDS;
        const uint32_t* Bb = Ab + 2048;
#pragma unroll
        for (int ks = 0; ks < 2; ks++) {
            const int fo = (((cb0 + (ks << 1)) ^ sw) << 2) + coff;
            uint32_t af[4][4], bf[4][2];
#pragma unroll
            for (int mt = 0; mt < 4; mt++) {
                const uint32_t* p = &Ab[((warp_m + mt*16 + g8) << 4) + fo];
                uint2 lo = *(const uint2*)p;
                uint2 hi = *(const uint2*)(p + 128);
                af[mt][0] = lo.x; af[mt][1] = hi.x;
                af[mt][2] = lo.y; af[mt][3] = hi.y;
            }
#pragma unroll
            for (int nt = 0; nt < 4; nt++) {
                uint2 u = *(const uint2*)&Bb[((warp_n + nt*8 + g8) << 4) + fo];
                bf[nt][0] = u.x; bf[nt][1] = u.y;
            }
#pragma unroll
            for (int mt = 0; mt < 4; mt++)
#pragma unroll
                for (int nt = 0; nt < 4; nt++)
                    MMA_TF32(acc[mt][nt], af[mt], bf[nt][0], bf[nt][1]);
        }
    }

    if (MODE == 0 || MODE == 1) {
#pragma unroll
        for (int mt = 0; mt < 4; mt++) {
#pragma unroll
            for (int nt = 0; nt < 4; nt++) {
                const size_t row = brow0 + warp_m + mt*16 + g8;
                const int    col = bcol0 + warp_n + nt*8 + tg*2;
                const float b0 = bias[col], b1 = bias[col + 1];
                float2 v0, v1;
                if (MODE == 1) {
                    v0 = { tf32f(acc[mt][nt][0] + b0), tf32f(acc[mt][nt][1] + b1) };
                    v1 = { tf32f(acc[mt][nt][2] + b0), tf32f(acc[mt][nt][3] + b1) };
                } else {
                    v0 = { acc[mt][nt][0] + b0, acc[mt][nt][1] + b1 };
                    v1 = { acc[mt][nt][2] + b0, acc[mt][nt][3] + b1 };
                }
                *(float2*)(C + row * N + col)       = v0;
                *(float2*)(C + (row + 8) * N + col) = v1;
            }
        }
    } else {
        // RoPE epilogue: stage acc+bias in smem [128][130], then rotate+rna
        float* st = (float*)gsm;
        __syncthreads();   // mainloop smem reads complete in ALL warps
#pragma unroll
        for (int mt = 0; mt < 4; mt++) {
#pragma unroll
            for (int nt = 0; nt < 4; nt++) {
                const int rl  = warp_m + mt*16 + g8;
                const int col = warp_n + nt*8 + tg*2;
                const float b0 = bias[bcol0 + col], b1 = bias[bcol0 + col + 1];
                float2 v0 = { acc[mt][nt][0] + b0, acc[mt][nt][1] + b1 };
                float2 v1 = { acc[mt][nt][2] + b0, acc[mt][nt][3] + b1 };
                *(float2*)&st[rl * 130 + col]       = v0;
                *(float2*)&st[(rl + 8) * 130 + col] = v1;
            }
        }
        __syncthreads();
        for (int i = tid; i < 128*64; i += 256) {
            int r = i >> 6, d = i & 63;
            float x1 = st[r*130 + d];
            float x2 = st[r*130 + d + 64];
            int s = (int)((brow0 + r) & (SEQ-1));
            float c  = cs[s*64 + d];
            float si = sn[s*64 + d];
            int p1 = (d & 56)        + kslot(d & 7);
            int p2 = ((d + 64) & ~7) + kslot(d & 7);
            float* rowp = C + (brow0 + r) * N + bcol0;
            rowp[p1] = tf32f((x1*c - x2*si) * ropescale);
            rowp[p2] = tf32f((x1*si + x2*c) * ropescale);
        }
    }
}

// Plain GEMM (out-projection)
__global__ __launch_bounds__(256, 2) void gemm_tf32(
    const float* __restrict__ A, const float* __restrict__ Bt,
    const float* __restrict__ bias, float* __restrict__ C,
    int M, int N, int K)
{
    extern __shared__ uint32_t gsm[];
    const size_t brow0 = (size_t)blockIdx.y * 128;
    const int    bcol0 = blockIdx.x * 128;
    gemm_body<0>(gsm, A + brow0 * K, Bt + (size_t)bcol0 * K, bias, C,
                 brow0, bcol0, N, K, nullptr, nullptr, 0.f);
}

// Fused Q + KV projection WITH RoPE/rna epilogues.
// 24 column-blocks: 0..15 Q (rope, qsc), 16..19 K (rope, 1.0), 20..23 V (rna).
__global__ __launch_bounds__(256, 2) void gemm_qkv(
    const float* __restrict__ A,
    const float* __restrict__ Wqt, const float* __restrict__ Wkvt,
    const float* __restrict__ bq,  const float* __restrict__ bkv,
    float* __restrict__ Cq, float* __restrict__ Ckv,
    const float* __restrict__ cs, const float* __restrict__ sn, int K)
{
    extern __shared__ uint32_t gsm[];
    const size_t brow0 = (size_t)blockIdx.y * 128;
    const int bx = blockIdx.x;
    const float qsc = 0.08838834764831845f * 1.4426950408889634f;
    if (bx < QDIM/128) {
        const int bcol0 = bx * 128;
        gemm_body<2>(gsm, A + brow0 * K, Wqt + (size_t)bcol0 * K, bq, Cq,
                     brow0, bcol0, QDIM, K, cs, sn, qsc);
    } else if (bx < QDIM/128 + 4) {
        const int bcol0 = (bx - QDIM/128) * 128;
        gemm_body<2>(gsm, A + brow0 * K, Wkvt + (size_t)bcol0 * K, bkv, Ckv,
                     brow0, bcol0, KVDIM, K, cs, sn, 1.0f);
    } else {
        const int bcol0 = (bx - QDIM/128) * 128;
        gemm_body<1>(gsm, A + brow0 * K, Wkvt + (size_t)bcol0 * K, bkv, Ckv,
                     brow0, bcol0, KVDIM, K, nullptr, nullptr, 0.f);
    }
}

// ---------------------------------------------------------------------------
// Flash attention, tf32 mma.sync — EXACT R13/R10 version (best known).
// Single-buffered K/V; K group then V group (V overlaps S+softmax).
// ---------------------------------------------------------------------------
#define KV_W 136
#define KV_WORDS (64*KV_W)               // 8704
#define PW_W 72
#define PS_OFF   (2*KV_WORDS)
#define FA_SMEM ((2*KV_WORDS + 8*16*PW_W) * 4)   // 106496 B

__global__ __launch_bounds__(256) void flash_tf32(
    const float* __restrict__ Q, const float* __restrict__ KV,
    float* __restrict__ O, const int* __restrict__ causal_p)
{
    extern __shared__ uint32_t fsm[];
    uint32_t* Ks = fsm;                  // [64*136]
    uint32_t* Vs = fsm + KV_WORDS;       // [64*136]
    uint32_t* Ps = fsm + PS_OFF;         // [8][16*72]

    const int causal = *causal_p;
    const int qt = gridDim.x - 1 - blockIdx.x;   // heavy tiles first
    const int h = blockIdx.y, b = blockIdx.z;
    const int q0 = qt << 7;
    const int tid = threadIdx.x;
    const int lane = tid & 31, wid = tid >> 5;
    const int g8 = lane >> 2, tg = lane & 3;
    const int m0 = wid << 4;
    const int sl0 = kslot(2*tg), sl1 = kslot(2*tg + 1);

    // ---- stage Q (permuted) via cp.async into fsm[128][136]
    const float* Qb = Q + ((size_t)(b*SEQ + q0))*QDIM + h*HD;
    for (int i = tid; i < 128*32; i += 256) {
        int r = i >> 5, c4 = (i & 31) << 2;
        CP16(SPTR(&fsm[r*KV_W + c4]), Qb + (size_t)r*QDIM + c4);
    }
    CP_COMMIT(); CP_WAIT0();
    __syncthreads();

    uint32_t aq[16][4];
#pragma unroll
    for (int kb = 0; kb < 16; kb++) {
        const uint32_t* p = &fsm[(m0 + g8)*KV_W + kb*8 + 2*tg];
        uint2 lo = *(const uint2*)p;
        uint2 hi = *(const uint2*)(p + 8*KV_W);
        aq[kb][0] = lo.x; aq[kb][2] = lo.y;
        aq[kb][1] = hi.x; aq[kb][3] = hi.y;
    }

    float m_[2] = { -1e30f, -1e30f }, l_[2] = { 0.f, 0.f };
    float oacc[16][4];
#pragma unroll
    for (int nt = 0; nt < 16; nt++)
#pragma unroll
        for (int c = 0; c < 4; c++) oacc[nt][c] = 0.f;

    const int full = causal ? (q0 >> 6) : (1 << 30);
    const int nkt  = causal ? ((q0 >> 6) + 2) : (SEQ >> 6);
    const float* Kb = KV + (size_t)(b*SEQ)*KVDIM + (h >> 2)*HD;
    uint32_t* Pw = Ps + wid*16*PW_W;

    for (int kt = 0; kt < nkt; kt++) {
        __syncthreads();                 // prev tile fully consumed
        // ---- K group
        for (int i = tid; i < 64*32; i += 256) {
            int r = i >> 5, c4 = (i & 31) << 2;
            CP16(SPTR(&Ks[r*KV_W + c4]),
                 Kb + (size_t)((kt << 6) + r)*KVDIM + c4);
        }
        CP_COMMIT();
        // ---- V group (overlaps with S + softmax below)
        for (int i = tid; i < 64*32; i += 256) {
            int r = i >> 5, c4 = (i & 31) << 2;
            CP16(SPTR(&Vs[r*KV_W + c4]),
                 Kb + (size_t)((kt << 6) + r)*KVDIM + NKV*HD + c4);
        }
        CP_COMMIT();
        CP_WAIT1();                      // K arrived (V may still be in flight)
        __syncthreads();

        // ---- S = Q K^T (permuted frags, LDS.64)
        float sacc[8][4];
#pragma unroll
        for (int nt = 0; nt < 8; nt++)
#pragma unroll
            for (int c = 0; c < 4; c++) sacc[nt][c] = 0.f;

#pragma unroll
        for (int kb = 0; kb < 16; kb++) {
            uint32_t bf[8][2];
#pragma unroll
            for (int nt = 0; nt < 8; nt++) {
                uint2 u = *(const uint2*)&Ks[(nt*8 + g8)*KV_W + kb*8 + 2*tg];
                bf[nt][0] = u.x;
                bf[nt][1] = u.y;
            }
#pragma unroll
            for (int nt = 0; nt < 8; nt++)
                MMA_TF32(sacc[nt], aq[kb], bf[nt][0], bf[nt][1]);
        }

        // ---- causal mask
        if (causal && kt >= full) {
            const int row0 = q0 + m0 + g8, row1 = row0 + 8;
#pragma unroll
            for (int nt = 0; nt < 8; nt++) {
                int col = (kt << 6) + nt*8 + tg*2;
                if (col     > row0) sacc[nt][0] = -1e30f;
                if (col + 1 > row0) sacc[nt][1] = -1e30f;
                if (col     > row1) sacc[nt][2] = -1e30f;
                if (col + 1 > row1) sacc[nt][3] = -1e30f;
            }
        }

        // ---- online softmax; P into PERMUTED slots
        float rm0 = -1e30f, rm1 = -1e30f;
#pragma unroll
        for (int nt = 0; nt < 8; nt++) {
            rm0 = fmaxf(rm0, fmaxf(sacc[nt][0], sacc[nt][1]));
            rm1 = fmaxf(rm1, fmaxf(sacc[nt][2], sacc[nt][3]));
        }
        rm0 = fmaxf(rm0, __shfl_xor_sync(0xffffffffu, rm0, 1));
        rm0 = fmaxf(rm0, __shfl_xor_sync(0xffffffffu, rm0, 2));
        rm1 = fmaxf(rm1, __shfl_xor_sync(0xffffffffu, rm1, 1));
        rm1 = fmaxf(rm1, __shfl_xor_sync(0xffffffffu, rm1, 2));

        float mn0 = fmaxf(m_[0], rm0), mn1 = fmaxf(m_[1], rm1);
        float f0 = ex2f(m_[0] - mn0), f1 = ex2f(m_[1] - mn1);
        float rs0 = 0.f, rs1 = 0.f;
#pragma unroll
        for (int nt = 0; nt < 8; nt++) {
            float p00 = ex2f(sacc[nt][0] - mn0);
            float p01 = ex2f(sacc[nt][1] - mn0);
            float p10 = ex2f(sacc[nt][2] - mn1);
            float p11 = ex2f(sacc[nt][3] - mn1);
            rs0 += p00 + p01; rs1 += p10 + p11;
            Pw[g8*PW_W + nt*8 + sl0]     = tf32_rna(p00);
            Pw[g8*PW_W + nt*8 + sl1]     = tf32_rna(p01);
            Pw[(g8+8)*PW_W + nt*8 + sl0] = tf32_rna(p10);
            Pw[(g8+8)*PW_W + nt*8 + sl1] = tf32_rna(p11);
        }
        rs0 += __shfl_xor_sync(0xffffffffu, rs0, 1);
        rs0 += __shfl_xor_sync(0xffffffffu, rs0, 2);
        rs1 += __shfl_xor_sync(0xffffffffu, rs1, 1);
        rs1 += __shfl_xor_sync(0xffffffffu, rs1, 2);
        l_[0] = l_[0]*f0 + rs0;  l_[1] = l_[1]*f1 + rs1;
        m_[0] = mn0;             m_[1] = mn1;
#pragma unroll
        for (int nt = 0; nt < 16; nt++) {
            oacc[nt][0] *= f0; oacc[nt][1] *= f0;
            oacc[nt][2] *= f1; oacc[nt][3] *= f1;
        }

        CP_WAIT0();                      // V arrived
        __syncthreads();                 // all threads' V copies visible

        // ---- O += P V (P frag via LDS.64)
#pragma unroll
        for (int kb = 0; kb < 8; kb++) {
            uint32_t ap[4];
            uint2 plo = *(const uint2*)&Pw[g8*PW_W + kb*8 + 2*tg];
            uint2 phi = *(const uint2*)&Pw[(g8+8)*PW_W + kb*8 + 2*tg];
            ap[0] = plo.x; ap[2] = plo.y;
            ap[1] = phi.x; ap[3] = phi.y;
#pragma unroll
            for (int nt = 0; nt < 16; nt++) {
                uint32_t b0 = Vs[(kb*8 + tg)*KV_W + nt*8 + g8];
                uint32_t b1 = Vs[(kb*8 + tg + 4)*KV_W + nt*8 + g8];
                MMA_TF32(oacc[nt], ap, b0, b1);
            }
        }
    }

    // ---- epilogue: O /= l, write rna'd into K-PERMUTED slots for out-proj
    const float inv0 = 1.0f / l_[0], inv1 = 1.0f / l_[1];
    const int s0 = (tg < 2) ? (tg << 2) : (((tg - 2) << 2) | 1);
    float* Ob = O + ((size_t)(b*SEQ + q0 + m0))*QDIM + h*HD;
#pragma unroll
    for (int nt = 0; nt < 16; nt++) {
        const int base = nt*8;
        Ob[(size_t)g8*QDIM + base + s0]         = tf32f(oacc[nt][0]*inv0);
        Ob[(size_t)g8*QDIM + base + s0 + 2]     = tf32f(oacc[nt][1]*inv0);
        Ob[(size_t)(g8+8)*QDIM + base + s0]     = tf32f(oacc[nt][2]*inv1);
        Ob[(size_t)(g8+8)*QDIM + base + s0 + 2] = tf32f(oacc[nt][3]*inv1);
    }
}

// ---------------------------------------------------------------------------
extern "C" void kernel_launch(void* const* d_in, const int* in_sizes, int n_in,
                              void* d_out, int out_size)
{
    const float* x    = (const float*)d_in[0];
    const float* cosp = (const float*)d_in[1];
    const float* sinp = (const float*)d_in[2];
    const float* Wq   = (const float*)d_in[3];
    const float* bq   = (const float*)d_in[4];
    const float* Wkv  = (const float*)d_in[5];
    const float* bkv  = (const float*)d_in[6];
    const float* Wo   = (const float*)d_in[7];
    const float* bo   = (const float*)d_in[8];
    const int*   causal = (const int*)d_in[9];
    float* out = (float*)d_out;

    float *x32, *q, *kv, *vo, *wqt, *wkvt, *wot;
    cudaGetSymbolAddress((void**)&x32,  g_x32);
    cudaGetSymbolAddress((void**)&q,    g_q);
    cudaGetSymbolAddress((void**)&kv,   g_kv);
    cudaGetSymbolAddress((void**)&vo,   g_vo);
    cudaGetSymbolAddress((void**)&wqt,  g_wqt);
    cudaGetSymbolAddress((void**)&wkvt, g_wkvt);
    cudaGetSymbolAddress((void**)&wot,  g_wot);

    cudaFuncSetAttribute(flash_tf32,
                         cudaFuncAttributeMaxDynamicSharedMemorySize, FA_SMEM);
    cudaFuncSetAttribute(gemm_tf32,
                         cudaFuncAttributeMaxDynamicSharedMemorySize, GEMM_SMEM);
    cudaFuncSetAttribute(gemm_qkv,
                         cudaFuncAttributeMaxDynamicSharedMemorySize, GEMM_SMEM);

    cvt_tf32_kernel<<<(ROWS*DIM/4 + 255)/256, 256>>>(x, x32, ROWS*DIM/4);
    transpose_w_kernel<<<dim3(64, 64, 3), dim3(32,8)>>>(Wq, Wkv, Wo,
                                                        wqt, wkvt, wot);

    // fused Q + KV projection + RoPE/rna epilogues (24 column-blocks)
    gemm_qkv<<<dim3((QDIM+KVDIM)/128, ROWS/128), 256, GEMM_SMEM>>>(
        x32, wqt, wkvt, bq, bkv, q, kv, cosp, sinp, DIM);

    flash_tf32<<<dim3(SEQ/128, NH, BATCH), 256, FA_SMEM>>>(q, kv, vo, causal);

    gemm_tf32<<<dim3(DIM/128, ROWS/128), 256, GEMM_SMEM>>>(vo, wot, bo, out, ROWS, DIM, DIM);
}

// round 17
// speedup vs baseline: 1.0180x; 1.0180x over previous
#include <cuda_runtime.h>
#include <cstdint>

#define BATCH 2
#define SEQ   2048
#define DIM   2048
#define NH    16
#define NKV   4
#define HD    128
#define QDIM  (NH*HD)      // 2048
#define KVDIM (2*NKV*HD)   // 1024
#define ROWS  (BATCH*SEQ)  // 4096

// Scratch (allocation-free rule: __device__ globals)
// K-PERMUTED layouts (per 8-elem k-group: [k0,k4,k1,k5,k2,k6,k3,k7]):
//   x32, wqt, wkvt, wot, vo            (gemm K dim)
//   g_q and K-half of g_kv (head dim)  (flash QK k dim)
__device__ float g_x32[(size_t)ROWS*DIM];
__device__ float g_q  [(size_t)ROWS*QDIM];
__device__ float g_kv [(size_t)ROWS*KVDIM];
__device__ float g_vo [(size_t)ROWS*QDIM];
__device__ float g_wqt [(size_t)DIM*QDIM];
__device__ float g_wkvt[(size_t)DIM*KVDIM];
__device__ float g_wot [(size_t)QDIM*DIM];

__device__ __forceinline__ uint32_t tf32_rna(float x) {
    uint32_t y;
    asm("cvt.rna.tf32.f32 %0, %1;" : "=r"(y) : "f"(x));
    return y;
}
__device__ __forceinline__ float tf32f(float x) {
    return __uint_as_float(tf32_rna(x));
}
__device__ __forceinline__ float ex2f(float x) {
    float y;
    asm("ex2.approx.ftz.f32 %0, %1;" : "=f"(y) : "f"(x));
    return y;
}
// slot(j) = ((j&3)<<1) | (j>>2)  for j in 0..7  -> [0,2,4,6,1,3,5,7]
__device__ __forceinline__ int kslot(int j) { return ((j & 3) << 1) | (j >> 2); }

#define MMA_TF32(c, a, b0, b1)                                                \
    asm volatile("mma.sync.aligned.m16n8k8.row.col.f32.tf32.tf32.f32 "        \
        "{%0,%1,%2,%3},{%4,%5,%6,%7},{%8,%9},{%0,%1,%2,%3};"                  \
        : "+f"((c)[0]), "+f"((c)[1]), "+f"((c)[2]), "+f"((c)[3])              \
        : "r"((a)[0]), "r"((a)[1]), "r"((a)[2]), "r"((a)[3]),                 \
          "r"(b0), "r"(b1))

#define CP16(d, s)   asm volatile("cp.async.cg.shared.global [%0], [%1], 16;" :: "r"(d), "l"(s))
#define CP_COMMIT()  asm volatile("cp.async.commit_group;")
#define CP_WAIT0()   asm volatile("cp.async.wait_group 0;")
#define CP_WAIT1()   asm volatile("cp.async.wait_group 1;")
#define CP_WAIT2()   asm volatile("cp.async.wait_group 2;")
#define SPTR(p)      ((uint32_t)__cvta_generic_to_shared(p))

// ---------------------------------------------------------------------------
// rna-convert x -> K-permuted layout
// ---------------------------------------------------------------------------
__global__ void cvt_tf32_kernel(const float* __restrict__ src,
                                float* __restrict__ dst, int n4)
{
    int i = blockIdx.x * blockDim.x + threadIdx.x;
    if (i < n4) {
        float4 v = ((const float4*)src)[i];
        size_t base = ((size_t)(i >> 1) << 3) + (i & 1);
        dst[base + 0] = tf32f(v.x);
        dst[base + 2] = tf32f(v.y);
        dst[base + 4] = tf32f(v.z);
        dst[base + 6] = tf32f(v.w);
    }
}

// ---------------------------------------------------------------------------
// Merged weight transpose + rna + K-permute: W[K,N] -> Wt[N,K]  (3 matrices)
// ---------------------------------------------------------------------------
__global__ void transpose_w_kernel(
    const float* __restrict__ Wq, const float* __restrict__ Wkv,
    const float* __restrict__ Wo,
    float* __restrict__ wqt, float* __restrict__ wkvt, float* __restrict__ wot)
{
    const float* src; float* dst; int K, N;
    if (blockIdx.z == 0)      { src = Wq;  dst = wqt;  K = DIM;  N = QDIM; }
    else if (blockIdx.z == 1) { src = Wkv; dst = wkvt; K = DIM;  N = KVDIM; }
    else                      { src = Wo;  dst = wot;  K = QDIM; N = DIM; }
    int n0 = blockIdx.x * 32, k0 = blockIdx.y * 32;
    if (n0 >= N || k0 >= K) return;

    __shared__ float t[32][33];
    int x = threadIdx.x, y = threadIdx.y;     // 32 x 8
#pragma unroll
    for (int i = 0; i < 32; i += 8)
        t[y + i][x] = src[(size_t)(k0 + y + i) * N + n0 + x];
    __syncthreads();
    int px = (x & 24) + kslot(x & 7);
#pragma unroll
    for (int i = 0; i < 32; i += 8)
        dst[(size_t)(n0 + y + i) * K + k0 + px] = tf32f(t[x][y + i]);
}

// ---------------------------------------------------------------------------
// Shared GEMM body (tf32 mma.sync, K-PERMUTED inputs, BK=16, FOUR-stage
// cp.async pipeline, 128x128 tile, 8 warps of 64x32).  (R15 version)
// ---------------------------------------------------------------------------
#define STG_WORDS 4096
#define GEMM_SMEM (4*STG_WORDS*4)        // 65536 B (2 CTAs/SM = 128 KB)

__device__ __forceinline__ void gemm_body(
    uint32_t* gsm,
    const float* __restrict__ Ag,
    const float* __restrict__ Bg,
    const float* __restrict__ bias,
    float* __restrict__ C,
    size_t brow0, int bcol0, int N, int K)
{
    const int tid  = threadIdx.x;
    const int lane = tid & 31, wid = tid >> 5;
    const int warp_m = (wid >> 2) << 6;
    const int warp_n = (wid & 3) << 5;
    const int g8 = lane >> 2, tg = lane & 3;
    const int sw   = g8 & 3;
    const int coff = (tg << 1) & 3;
    const int cb0  = tg >> 1;

    const int r0 = tid >> 2, cch = tid & 3;
    const int dxor = ((cch ^ (r0 & 3)) << 2);
    const int nk = K >> 4;

    auto issue = [&](int kt, int s) {
        uint32_t* Ad = gsm + s * STG_WORDS;
        uint32_t* Bd = Ad + 2048;
        const float* ap = Ag + (size_t)r0 * K + (kt << 4) + (cch << 2);
        const float* bp = Bg + (size_t)r0 * K + (kt << 4) + (cch << 2);
        CP16(SPTR(&Ad[(r0 << 4) + dxor]),        ap);
        CP16(SPTR(&Ad[((r0 + 64) << 4) + dxor]), ap + (size_t)64 * K);
        CP16(SPTR(&Bd[(r0 << 4) + dxor]),        bp);
        CP16(SPTR(&Bd[((r0 + 64) << 4) + dxor]), bp + (size_t)64 * K);
    };

    float acc[4][4][4];
#pragma unroll
    for (int i = 0; i < 4; i++)
#pragma unroll
        for (int j = 0; j < 4; j++)
#pragma unroll
            for (int c = 0; c < 4; c++) acc[i][j][c] = 0.f;

    issue(0, 0); CP_COMMIT();
    issue(1, 1); CP_COMMIT();
    issue(2, 2); CP_COMMIT();

    for (int kt = 0; kt < nk; kt++) {
        CP_WAIT2();
        __syncthreads();
        if (kt + 3 < nk) issue(kt + 3, (kt + 3) & 3);
        CP_COMMIT();

        const uint32_t* Ab = gsm + (kt & 3) * STG_WORDS;
        const uint32_t* Bb = Ab + 2048;
#pragma unroll
        for (int ks = 0; ks < 2; ks++) {
            const int fo = (((cb0 + (ks << 1)) ^ sw) << 2) + coff;
            uint32_t af[4][4], bf[4][2];
#pragma unroll
            for (int mt = 0; mt < 4; mt++) {
                const uint32_t* p = &Ab[((warp_m + mt*16 + g8) << 4) + fo];
                uint2 lo = *(const uint2*)p;
                uint2 hi = *(const uint2*)(p + 128);
                af[mt][0] = lo.x; af[mt][1] = hi.x;
                af[mt][2] = lo.y; af[mt][3] = hi.y;
            }
#pragma unroll
            for (int nt = 0; nt < 4; nt++) {
                uint2 u = *(const uint2*)&Bb[((warp_n + nt*8 + g8) << 4) + fo];
                bf[nt][0] = u.x; bf[nt][1] = u.y;
            }
#pragma unroll
            for (int mt = 0; mt < 4; mt++)
#pragma unroll
                for (int nt = 0; nt < 4; nt++)
                    MMA_TF32(acc[mt][nt], af[mt], bf[nt][0], bf[nt][1]);
        }
    }

#pragma unroll
    for (int mt = 0; mt < 4; mt++) {
#pragma unroll
        for (int nt = 0; nt < 4; nt++) {
            const size_t row = brow0 + warp_m + mt*16 + g8;
            const int    col = bcol0 + warp_n + nt*8 + tg*2;
            const float b0 = bias[col], b1 = bias[col + 1];
            float2 v0 = { acc[mt][nt][0] + b0, acc[mt][nt][1] + b1 };
            float2 v1 = { acc[mt][nt][2] + b0, acc[mt][nt][3] + b1 };
            *(float2*)(C + row * N + col)       = v0;
            *(float2*)(C + (row + 8) * N + col) = v1;
        }
    }
}

// Plain GEMM (out-projection)
__global__ __launch_bounds__(256, 2) void gemm_tf32(
    const float* __restrict__ A, const float* __restrict__ Bt,
    const float* __restrict__ bias, float* __restrict__ C,
    int M, int N, int K)
{
    extern __shared__ uint32_t gsm[];
    const size_t brow0 = (size_t)blockIdx.y * 128;
    const int    bcol0 = blockIdx.x * 128;
    gemm_body(gsm, A + brow0 * K, Bt + (size_t)bcol0 * K, bias, C,
              brow0, bcol0, N, K);
}

// Fused Q + KV projection (24 column-blocks: 16 Q + 8 KV)
__global__ __launch_bounds__(256, 2) void gemm_qkv(
    const float* __restrict__ A,
    const float* __restrict__ Wqt, const float* __restrict__ Wkvt,
    const float* __restrict__ bq,  const float* __restrict__ bkv,
    float* __restrict__ Cq, float* __restrict__ Ckv, int K)
{
    extern __shared__ uint32_t gsm[];
    const size_t brow0 = (size_t)blockIdx.y * 128;
    const int bx = blockIdx.x;
    if (bx < QDIM/128) {
        const int bcol0 = bx * 128;
        gemm_body(gsm, A + brow0 * K, Wqt + (size_t)bcol0 * K, bq, Cq,
                  brow0, bcol0, QDIM, K);
    } else {
        const int bcol0 = (bx - QDIM/128) * 128;
        gemm_body(gsm, A + brow0 * K, Wkvt + (size_t)bcol0 * K, bkv, Ckv,
                  brow0, bcol0, KVDIM, K);
    }
}

// ---------------------------------------------------------------------------
// RoPE + rna; Q and K written HEAD-DIM PERMUTED. V rna'd in place. (R15)
// ---------------------------------------------------------------------------
__global__ void rope_cvt_kernel(float* __restrict__ q, float* __restrict__ kv,
                                const float* __restrict__ cs,
                                const float* __restrict__ sn)
{
    const int row = blockIdx.x;
    const int s = row & (SEQ-1);
    const float qsc = 0.08838834764831845f * 1.4426950408889634f;
    for (int t = threadIdx.x; t < (NH+NKV)*64; t += blockDim.x) {
        int head = t >> 6, d = t & 63;
        float c  = cs[s*64 + d];
        float si = sn[s*64 + d];
        float* base; float sc;
        if (head < NH) { base = q  + (size_t)row*QDIM  + head*HD; sc = qsc; }
        else           { base = kv + (size_t)row*KVDIM + (head-NH)*HD; sc = 1.f; }
        float x1 = base[d], x2 = base[d + 64];
        int p1 = (d & 56)        + kslot(d & 7);
        int p2 = ((d + 64) & ~7) + kslot(d & 7);
        base[p1] = tf32f((x1*c - x2*si) * sc);
        base[p2] = tf32f((x1*si + x2*c) * sc);
    }
    float* vb = kv + (size_t)row*KVDIM + NKV*HD;
    for (int t = threadIdx.x; t < NKV*HD; t += blockDim.x)
        vb[t] = tf32f(vb[t]);
}

// ---------------------------------------------------------------------------
// Flash attention, tf32 mma.sync. R13 compute structure, but with
// DOUBLE-BUFFERED K/V tiles. Profile evidence (R16): flash is REGISTER-limited
// to 1 CTA/SM (regs=208), so the extra smem (176128 B < 227 KB) costs no
// occupancy, and prefetching tile kt+2 hides the K-load latency that was
// fully exposed each tile.
// ---------------------------------------------------------------------------
#define KV_W 136
#define KV_WORDS (64*KV_W)               // 8704
#define PW_W 72
#define PS_OFF   (4*KV_WORDS)            // 34816
#define FA_SMEM ((4*KV_WORDS + 8*16*PW_W) * 4)   // 176128 B

__global__ __launch_bounds__(256) void flash_tf32(
    const float* __restrict__ Q, const float* __restrict__ KV,
    float* __restrict__ O, const int* __restrict__ causal_p)
{
    extern __shared__ uint32_t fsm[];
    // [Ks0][Ks1][Vs0][Vs1][Ps]
    uint32_t* Vsb = fsm + 2*KV_WORDS;
    uint32_t* Ps  = fsm + PS_OFF;        // [8][16*72]

    const int causal = *causal_p;
    const int qt = gridDim.x - 1 - blockIdx.x;   // heavy tiles first
    const int h = blockIdx.y, b = blockIdx.z;
    const int q0 = qt << 7;
    const int tid = threadIdx.x;
    const int lane = tid & 31, wid = tid >> 5;
    const int g8 = lane >> 2, tg = lane & 3;
    const int m0 = wid << 4;
    const int sl0 = kslot(2*tg), sl1 = kslot(2*tg + 1);

    // ---- stage Q (permuted) via cp.async into fsm[128][136] (over Ks0+Ks1)
    const float* Qb = Q + ((size_t)(b*SEQ + q0))*QDIM + h*HD;
    for (int i = tid; i < 128*32; i += 256) {
        int r = i >> 5, c4 = (i & 31) << 2;
        CP16(SPTR(&fsm[r*KV_W + c4]), Qb + (size_t)r*QDIM + c4);
    }
    CP_COMMIT(); CP_WAIT0();
    __syncthreads();

    uint32_t aq[16][4];
#pragma unroll
    for (int kb = 0; kb < 16; kb++) {
        const uint32_t* p = &fsm[(m0 + g8)*KV_W + kb*8 + 2*tg];
        uint2 lo = *(const uint2*)p;
        uint2 hi = *(const uint2*)(p + 8*KV_W);
        aq[kb][0] = lo.x; aq[kb][2] = lo.y;
        aq[kb][1] = hi.x; aq[kb][3] = hi.y;
    }
    __syncthreads();   // ALL warps done reading Q; K buffers reusable

    float m_[2] = { -1e30f, -1e30f }, l_[2] = { 0.f, 0.f };
    float oacc[16][4];
#pragma unroll
    for (int nt = 0; nt < 16; nt++)
#pragma unroll
        for (int c = 0; c < 4; c++) oacc[nt][c] = 0.f;

    const int full = causal ? (q0 >> 6) : (1 << 30);
    const int nkt  = causal ? ((q0 >> 6) + 2) : (SEQ >> 6);
    const float* Kb = KV + (size_t)(b*SEQ)*KVDIM + (h >> 2)*HD;
    uint32_t* Pw = Ps + wid*16*PW_W;

    auto issue_kv = [&](int kt, int buf) {
        uint32_t* Kd = fsm + buf*KV_WORDS;
        uint32_t* Vd = Vsb + buf*KV_WORDS;
        for (int i = tid; i < 64*32; i += 256) {
            int r = i >> 5, c4 = (i & 31) << 2;
            const float* kp = Kb + (size_t)((kt << 6) + r)*KVDIM + c4;
            CP16(SPTR(&Kd[r*KV_W + c4]), kp);
            CP16(SPTR(&Vd[r*KV_W + c4]), kp + NKV*HD);
        }
    };

    issue_kv(0, 0); CP_COMMIT();
    if (nkt > 1) issue_kv(1, 1);
    CP_COMMIT();

    for (int kt = 0; kt < nkt; kt++) {
        CP_WAIT1();                      // tile kt arrived (kt+1 may fly)
        __syncthreads();
        const uint32_t* Ks = fsm + (kt & 1)*KV_WORDS;
        const uint32_t* Vs = Vsb + (kt & 1)*KV_WORDS;

        // ---- S = Q K^T (permuted frags, LDS.64)
        float sacc[8][4];
#pragma unroll
        for (int nt = 0; nt < 8; nt++)
#pragma unroll
            for (int c = 0; c < 4; c++) sacc[nt][c] = 0.f;

#pragma unroll
        for (int kb = 0; kb < 16; kb++) {
            uint32_t bf[8][2];
#pragma unroll
            for (int nt = 0; nt < 8; nt++) {
                uint2 u = *(const uint2*)&Ks[(nt*8 + g8)*KV_W + kb*8 + 2*tg];
                bf[nt][0] = u.x;
                bf[nt][1] = u.y;
            }
#pragma unroll
            for (int nt = 0; nt < 8; nt++)
                MMA_TF32(sacc[nt], aq[kb], bf[nt][0], bf[nt][1]);
        }

        // ---- causal mask
        if (causal && kt >= full) {
            const int row0 = q0 + m0 + g8, row1 = row0 + 8;
#pragma unroll
            for (int nt = 0; nt < 8; nt++) {
                int col = (kt << 6) + nt*8 + tg*2;
                if (col     > row0) sacc[nt][0] = -1e30f;
                if (col + 1 > row0) sacc[nt][1] = -1e30f;
                if (col     > row1) sacc[nt][2] = -1e30f;
                if (col + 1 > row1) sacc[nt][3] = -1e30f;
            }
        }

        // ---- online softmax; P into PERMUTED slots
        float rm0 = -1e30f, rm1 = -1e30f;
#pragma unroll
        for (int nt = 0; nt < 8; nt++) {
            rm0 = fmaxf(rm0, fmaxf(sacc[nt][0], sacc[nt][1]));
            rm1 = fmaxf(rm1, fmaxf(sacc[nt][2], sacc[nt][3]));
        }
        rm0 = fmaxf(rm0, __shfl_xor_sync(0xffffffffu, rm0, 1));
        rm0 = fmaxf(rm0, __shfl_xor_sync(0xffffffffu, rm0, 2));
        rm1 = fmaxf(rm1, __shfl_xor_sync(0xffffffffu, rm1, 1));
        rm1 = fmaxf(rm1, __shfl_xor_sync(0xffffffffu, rm1, 2));

        float mn0 = fmaxf(m_[0], rm0), mn1 = fmaxf(m_[1], rm1);
        float f0 = ex2f(m_[0] - mn0), f1 = ex2f(m_[1] - mn1);
        float rs0 = 0.f, rs1 = 0.f;
#pragma unroll
        for (int nt = 0; nt < 8; nt++) {
            float p00 = ex2f(sacc[nt][0] - mn0);
            float p01 = ex2f(sacc[nt][1] - mn0);
            float p10 = ex2f(sacc[nt][2] - mn1);
            float p11 = ex2f(sacc[nt][3] - mn1);
            rs0 += p00 + p01; rs1 += p10 + p11;
            Pw[g8*PW_W + nt*8 + sl0]     = tf32_rna(p00);
            Pw[g8*PW_W + nt*8 + sl1]     = tf32_rna(p01);
            Pw[(g8+8)*PW_W + nt*8 + sl0] = tf32_rna(p10);
            Pw[(g8+8)*PW_W + nt*8 + sl1] = tf32_rna(p11);
        }
        rs0 += __shfl_xor_sync(0xffffffffu, rs0, 1);
        rs0 += __shfl_xor_sync(0xffffffffu, rs0, 2);
        rs1 += __shfl_xor_sync(0xffffffffu, rs1, 1);
        rs1 += __shfl_xor_sync(0xffffffffu, rs1, 2);
        l_[0] = l_[0]*f0 + rs0;  l_[1] = l_[1]*f1 + rs1;
        m_[0] = mn0;             m_[1] = mn1;
#pragma unroll
        for (int nt = 0; nt < 16; nt++) {
            oacc[nt][0] *= f0; oacc[nt][1] *= f0;
            oacc[nt][2] *= f1; oacc[nt][3] *= f1;
        }
        __syncwarp();

        // ---- O += P V (P frag via LDS.64)
#pragma unroll
        for (int kb = 0; kb < 8; kb++) {
            uint32_t ap[4];
            uint2 plo = *(const uint2*)&Pw[g8*PW_W + kb*8 + 2*tg];
            uint2 phi = *(const uint2*)&Pw[(g8+8)*PW_W + kb*8 + 2*tg];
            ap[0] = plo.x; ap[2] = plo.y;
            ap[1] = phi.x; ap[3] = phi.y;
#pragma unroll
            for (int nt = 0; nt < 16; nt++) {
                uint32_t b0 = Vs[(kb*8 + tg)*KV_W + nt*8 + g8];
                uint32_t b1 = Vs[(kb*8 + tg + 4)*KV_W + nt*8 + g8];
                MMA_TF32(oacc[nt], ap, b0, b1);
            }
        }

        __syncthreads();                 // tile kt buffers fully consumed
        if (kt + 2 < nkt) issue_kv(kt + 2, kt & 1);
        CP_COMMIT();
    }

    // ---- epilogue: O /= l, write rna'd into K-PERMUTED slots for out-proj
    const float inv0 = 1.0f / l_[0], inv1 = 1.0f / l_[1];
    const int s0 = (tg < 2) ? (tg << 2) : (((tg - 2) << 2) | 1);
    float* Ob = O + ((size_t)(b*SEQ + q0 + m0))*QDIM + h*HD;
#pragma unroll
    for (int nt = 0; nt < 16; nt++) {
        const int base = nt*8;
        Ob[(size_t)g8*QDIM + base + s0]         = tf32f(oacc[nt][0]*inv0);
        Ob[(size_t)g8*QDIM + base + s0 + 2]     = tf32f(oacc[nt][1]*inv0);
        Ob[(size_t)(g8+8)*QDIM + base + s0]     = tf32f(oacc[nt][2]*inv1);
        Ob[(size_t)(g8+8)*QDIM + base + s0 + 2] = tf32f(oacc[nt][3]*inv1);
    }
}

// ---------------------------------------------------------------------------
extern "C" void kernel_launch(void* const* d_in, const int* in_sizes, int n_in,
                              void* d_out, int out_size)
{
    const float* x    = (const float*)d_in[0];
    const float* cosp = (const float*)d_in[1];
    const float* sinp = (const float*)d_in[2];
    const float* Wq   = (const float*)d_in[3];
    const float* bq   = (const float*)d_in[4];
    const float* Wkv  = (const float*)d_in[5];
    const float* bkv  = (const float*)d_in[6];
    const float* Wo   = (const float*)d_in[7];
    const float* bo   = (const float*)d_in[8];
    const int*   causal = (const int*)d_in[9];
    float* out = (float*)d_out;

    float *x32, *q, *kv, *vo, *wqt, *wkvt, *wot;
    cudaGetSymbolAddress((void**)&x32,  g_x32);
    cudaGetSymbolAddress((void**)&q,    g_q);
    cudaGetSymbolAddress((void**)&kv,   g_kv);
    cudaGetSymbolAddress((void**)&vo,   g_vo);
    cudaGetSymbolAddress((void**)&wqt,  g_wqt);
    cudaGetSymbolAddress((void**)&wkvt, g_wkvt);
    cudaGetSymbolAddress((void**)&wot,  g_wot);

    cudaFuncSetAttribute(flash_tf32,
                         cudaFuncAttributeMaxDynamicSharedMemorySize, FA_SMEM);
    cudaFuncSetAttribute(gemm_tf32,
                         cudaFuncAttributeMaxDynamicSharedMemorySize, GEMM_SMEM);
    cudaFuncSetAttribute(gemm_qkv,
                         cudaFuncAttributeMaxDynamicSharedMemorySize, GEMM_SMEM);

    cvt_tf32_kernel<<<(ROWS*DIM/4 + 255)/256, 256>>>(x, x32, ROWS*DIM/4);
    transpose_w_kernel<<<dim3(64, 64, 3), dim3(32,8)>>>(Wq, Wkv, Wo,
                                                        wqt, wkvt, wot);

    // fused Q + KV projection (24 column-blocks: 16 Q, 8 KV)
    gemm_qkv<<<dim3((QDIM+KVDIM)/128, ROWS/128), 256, GEMM_SMEM>>>(
        x32, wqt, wkvt, bq, bkv, q, kv, DIM);

    rope_cvt_kernel<<<ROWS, 256>>>(q, kv, cosp, sinp);

    flash_tf32<<<dim3(SEQ/128, NH, BATCH), 256, FA_SMEM>>>(q, kv, vo, causal);

    gemm_tf32<<<dim3(DIM/128, ROWS/128), 256, GEMM_SMEM>>>(vo, wot, bo, out, ROWS, DIM, DIM);
}